// round 10
// baseline (speedup 1.0000x reference)
#include <cuda_runtime.h>
#include <math_constants.h>
#include <cooperative_groups.h>

namespace cg = cooperative_groups;

#define NCLS   20
#define NBOX   400
#define SORTN  512
#define IMGW   1333.0f
#define IMGH   800.0f
#define TOPK   100
#define NSEL   (NCLS * TOPK)     // 2000
#define NW     13                // 400 bits -> 13 u32 words
#define CSZ    8                 // cluster size (portable max)
#define RPC    50                // rows per cluster CTA (8*50=400)
#define SENTK  0xFFFFFFFFFFFFFFFFull
#define FULLM  0xFFFFFFFFu

// ---------------- device scratch ----------------
__device__ unsigned long long g_skey[NCLS * SORTN];   // sorted keys per class
__device__ float4             g_sbox[NCLS * NBOX];    // clipped boxes in sorted order
__device__ int                g_m[NCLS];              // valid count per class
__device__ unsigned long long g_selkey[NSEL];         // per class: sorted kept top-100 (pad)
__device__ unsigned int       g_maxBits = 0u;
__device__ unsigned int       g_T       = 0u;
__device__ unsigned int       g_done    = 0u;
__device__ unsigned int       g_done2   = 0u;

// descending-sortable mapping (ascending u64 sort -> descending float score)
__device__ __forceinline__ unsigned int ord_desc(float f) {
    unsigned int u = __float_as_uint(f);
    unsigned int m = (u & 0x80000000u) ? ~u : (u | 0x80000000u);
    return ~m;
}
__device__ __forceinline__ float inv_ord(unsigned int o) {
    unsigned int m = ~o;
    unsigned int u = (m & 0x80000000u) ? (m & 0x7FFFFFFFu) : ~m;
    return __uint_as_float(u);
}
__device__ __forceinline__ unsigned long long shfl_xor_u64(unsigned long long v, int jj) {
    unsigned int lo = (unsigned int)v, hi = (unsigned int)(v >> 32);
    lo = __shfl_xor_sync(FULLM, lo, jj);
    hi = __shfl_xor_sync(FULLM, hi, jj);
    return ((unsigned long long)hi << 32) | lo;
}
__device__ __forceinline__ unsigned long long uminll(unsigned long long a, unsigned long long b) { return a < b ? a : b; }
__device__ __forceinline__ unsigned long long umaxll(unsigned long long a, unsigned long long b) { return a > b ? a : b; }

// ---------------- k1: per-class load/clip/key + hybrid bitonic sort (proven) ----------------
__global__ void __launch_bounds__(SORTN) k1(const float* __restrict__ boxes,
                                            const float* __restrict__ scores) {
    __shared__ unsigned long long skey[SORTN];
    __shared__ float4       s_cbox[NBOX];
    __shared__ unsigned int s_wmax[16];

    const int cls = blockIdx.x, tid = threadIdx.x, lane = tid & 31;

    float lmax = 0.0f;
    bool  valid = false;
    unsigned long long v = SENTK;
    if (tid < NBOX) {
        float4 bx = reinterpret_cast<const float4*>(boxes)[cls * NBOX + tid];
        float2 sc = reinterpret_cast<const float2*>(scores)[cls * NBOX + tid];
        bool fin = isfinite(bx.x) && isfinite(bx.y) && isfinite(bx.z) && isfinite(bx.w)
                && isfinite(sc.x) && isfinite(sc.y);
        float x1 = fminf(fmaxf(bx.x, 0.0f), IMGW);
        float y1 = fminf(fmaxf(bx.y, 0.0f), IMGH);
        float x2 = fminf(fmaxf(bx.z, 0.0f), IMGW);
        float y2 = fminf(fmaxf(bx.w, 0.0f), IMGH);
        valid = fin && (sc.x > 0.05f);
        float masked = valid ? sc.x : -CUDART_INF_F;
        unsigned int j = (unsigned int)(tid * NCLS + cls);       // transposed index
        v = ((unsigned long long)ord_desc(masked) << 32) | j;
        s_cbox[tid] = make_float4(x1, y1, x2, y2);
        lmax = fmaxf(fmaxf(x1, x2), fmaxf(y1, y2));
    }
    unsigned int wb = __reduce_max_sync(FULLM, __float_as_uint(lmax));
    if (lane == 0) s_wmax[tid >> 5] = wb;
    const int m = __syncthreads_count(valid);
    if (tid == 0) {
        unsigned int mx = 0;
        #pragma unroll
        for (int w = 0; w < 16; w++) mx = max(mx, s_wmax[w]);
        atomicMax(&g_maxBits, mx);
    }

    // hybrid bitonic sort: smem stages jj>=32, shfl stages jj<=16
    for (int k = 2; k <= SORTN; k <<= 1) {
        for (int jj = k >> 1; jj >= 32; jj >>= 1) {
            skey[tid] = v;
            __syncthreads();
            unsigned long long p = skey[tid ^ jj];
            bool km = (((tid & k) == 0) == ((tid & jj) == 0));
            v = km ? uminll(v, p) : umaxll(v, p);
            __syncthreads();
        }
        int j0 = (k >> 1) < 16 ? (k >> 1) : 16;
        for (int jj = j0; jj >= 1; jj >>= 1) {
            unsigned long long p = shfl_xor_u64(v, jj);
            bool km = (((tid & k) == 0) == ((tid & jj) == 0));
            v = km ? uminll(v, p) : umaxll(v, p);
        }
    }

    g_skey[cls * SORTN + tid] = v;
    if (tid < m) {
        unsigned int j = (unsigned int)v;
        int b = (int)(j / NCLS);
        g_sbox[cls * NBOX + tid] = s_cbox[b];
    }
    if (tid == 0) g_m[cls] = m;
}

// ---------------- k2f: clustered mask (DSMEM into rank 0) + greedy + merge + output -------
__global__ void __cluster_dims__(CSZ, 1, 1) __launch_bounds__(512, 2)
k2f(const float* __restrict__ boxes, const int* __restrict__ pred_cls,
    float* __restrict__ out)
{
    // u_raw: mask (20.8KB) during greedy -> sel (16KB) during merge
    __shared__ __align__(16) unsigned char u_raw[NBOX * NW * 4];
    __shared__ __align__(16) float4 s_b[NBOX];                 // 6.4 KB shifted boxes
    __shared__ float              s_a[NBOX];                   // 1.6 KB areas
    __shared__ unsigned long long s_skey[SORTN];               // 4 KB (rank 0 only)
    __shared__ int s_T;

    unsigned int*       s_mask = reinterpret_cast<unsigned int*>(u_raw);
    unsigned long long* s_sel  = reinterpret_cast<unsigned long long*>(u_raw);

    cg::cluster_group cluster = cg::this_cluster();
    const unsigned rank = cluster.block_rank();
    const int c    = blockIdx.x / CSZ;            // class = cluster id
    const int tid  = threadIdx.x;
    const int lane = tid & 31;
    const int m    = g_m[c];

    const float offv  = __fadd_rn(__uint_as_float(g_maxBits), 1.0f);
    const float shift = __fmul_rn((float)c, offv);

    // every CTA stages shifted boxes + areas locally (L2-broadcast reads)
    for (int t = tid; t < m; t += 512) {
        float4 bx = g_sbox[c * NBOX + t];
        float4 sb = make_float4(__fadd_rn(bx.x, shift), __fadd_rn(bx.y, shift),
                                __fadd_rn(bx.z, shift), __fadd_rn(bx.w, shift));
        s_b[t] = sb;
        s_a[t] = __fmul_rn(__fsub_rn(sb.z, sb.x), __fsub_rn(sb.w, sb.y));
    }
    if (rank == 0) {
        for (int t = tid; t < SORTN; t += 512) s_skey[t] = g_skey[c * SORTN + t];
    }
    __syncthreads();

    // compute this CTA's 50-row mask tile, store words directly into rank 0's smem
    unsigned int* dmask = (unsigned int*)cluster.map_shared_rank((void*)s_mask, 0);
    const int base_row = (int)rank * RPC;
    for (int lin = tid; lin < RPC * NW; lin += 512) {
        int rl = lin / NW;
        int w  = lin - rl * NW;
        int i  = base_row + rl;
        if (i < m) {
            unsigned int bits = 0;
            const int lo = w * 32;
            const int hi = min(m, lo + 32);
            const int st = max(lo, i + 1);
            if (st < hi) {
                float4 bi = s_b[i];
                float  ai = s_a[i];
                for (int jd = st; jd < hi; jd++) {
                    float4 bj = s_b[jd];
                    float iw = fmaxf(__fsub_rn(fminf(bi.z, bj.z), fmaxf(bi.x, bj.x)), 0.0f);
                    float ih = fmaxf(__fsub_rn(fminf(bi.w, bj.w), fmaxf(bi.y, bj.y)), 0.0f);
                    float inter = __fmul_rn(iw, ih);
                    float uni = __fsub_rn(__fadd_rn(ai, s_a[jd]), inter);
                    float iou = (uni > 0.0f) ? __fdiv_rn(inter, uni) : 0.0f;
                    if (iou > 0.5f) bits |= 1u << (jd - lo);
                }
            }
            dmask[i * NW + w] = bits;             // DSMEM store to rank 0
        }
    }
    cluster.sync();                                // mask complete + visible in rank 0
    if (rank != 0) return;                         // no further DSMEM targets these CTAs

    // ---------- rank 0: greedy scan (warp 0, register-batched) + emit kept top-100 ----------
    if (tid < 32) {
        unsigned int mysup = 0;                    // lane w owns rows [32w, 32w+32)
        const int nb = (m + 31) >> 5;
        for (int b = 0; b < nb; b++) {
            unsigned int cur = __shfl_sync(FULLM, mysup, b);
            const int base = b << 5;
            const int rows = min(32, m - base);
            unsigned int wreg[32];
            #pragma unroll
            for (int q = 0; q < 32; q++)
                wreg[q] = (q < rows) ? s_mask[(base + q) * NW + b] : 0u;
            #pragma unroll
            for (int q = 0; q < 32; q++) {
                if (q < rows && !((cur >> q) & 1u)) {
                    cur |= wreg[q];
                    if (lane < NW) mysup |= s_mask[(base + q) * NW + lane];
                }
            }
        }
        int cnt = 0;
        for (int bs = 0; bs < m; bs += 32) {
            int t = bs + lane;
            unsigned int supw = __shfl_sync(FULLM, mysup, t >> 5);
            bool kept = (t < m) && !((supw >> (t & 31)) & 1u);
            unsigned int bal = __ballot_sync(FULLM, kept);
            int pos = cnt + __popc(bal & ((1u << lane) - 1u));
            if (kept && pos < TOPK) g_selkey[c * TOPK + pos] = s_skey[t];
            cnt += __popc(bal);
        }
        cnt = min(cnt, TOPK);
        for (int p = cnt + lane; p < TOPK; p += 32) g_selkey[c * TOPK + p] = SENTK;
        __threadfence();                           // publish selkey stores
        __syncwarp();
        if (lane == 0) {
            atomicAdd(&g_T, (unsigned int)cnt);
            __threadfence();
            atomicAdd(&g_done, 1u);
        }
    }
    __syncthreads();

    // rendezvous: all 20 classes' selkey visible (identical code paths -> tiny skew)
    if (tid == 0) {
        volatile unsigned int* vd = &g_done;
        while (*vd < (unsigned)NCLS) { }
        __threadfence();
        s_T = (int)*(volatile unsigned int*)&g_T;
    }
    __syncthreads();                               // s_mask dead; s_sel alias live next

    for (int t = tid; t < NSEL; t += 512) s_sel[t] = g_selkey[t];
    __syncthreads();

    // cluster 0 fills default rows [T, 100)
    if (c == 0) {
        for (int r = s_T + tid; r < TOPK; r += 512) {
            out[r * 4 + 0] = 0.0f;
            out[r * 4 + 1] = 0.0f;
            out[r * 4 + 2] = 0.0f;
            out[r * 4 + 3] = 0.0f;
            out[4 * TOPK + r] = 0.0f;
            out[5 * TOPK + r] = -1.0f;
            out[6 * TOPK + r] = 0.0f;
        }
    }

    // merge-by-rank: rank own class's kept keys against the other 19 sorted lists
    if (tid < TOPK) {
        unsigned long long e = s_sel[c * TOPK + tid];
        if (e != SENTK) {
            int rankk = tid;                       // position within own sorted list
            #pragma unroll
            for (int c2 = 0; c2 < NCLS; c2++) {
                if (c2 == c) continue;
                const unsigned long long* seg = s_sel + c2 * TOPK;
                int lo = 0;                        // lower_bound: #elements < e
                #pragma unroll
                for (int s = 64; s > 0; s >>= 1) {
                    int p = lo + s;
                    if (p <= TOPK && seg[p - 1] < e) lo = p;
                }
                rankk += lo;
            }
            if (rankk < TOPK) {
                unsigned int j = (unsigned int)e;
                int cc = (int)(j % NCLS);
                int b  = (int)(j / NCLS);
                int i  = cc * NBOX + b;
                float4 bx = reinterpret_cast<const float4*>(boxes)[i];
                out[rankk * 4 + 0] = fminf(fmaxf(bx.x, 0.0f), IMGW);
                out[rankk * 4 + 1] = fminf(fmaxf(bx.y, 0.0f), IMGH);
                out[rankk * 4 + 2] = fminf(fmaxf(bx.z, 0.0f), IMGW);
                out[rankk * 4 + 3] = fminf(fmaxf(bx.w, 0.0f), IMGH);
                out[4 * TOPK + rankk] = inv_ord((unsigned int)(e >> 32));
                out[5 * TOPK + rankk] = (float)pred_cls[i];
                out[6 * TOPK + rankk] = 1.0f;
            }
        }
    }

    // last finisher resets globals for the next graph replay
    __syncthreads();
    if (tid == 0) {
        unsigned int r2 = atomicAdd(&g_done2, 1u);
        if (r2 == NCLS - 1) {
            g_maxBits = 0u;
            g_T       = 0u;
            g_done    = 0u;
            g_done2   = 0u;
            __threadfence();
        }
    }
}

// ---------------- launch ----------------
extern "C" void kernel_launch(void* const* d_in, const int* in_sizes, int n_in,
                              void* d_out, int out_size) {
    const int*   pred_cls = (const int*)d_in[0];
    const float* boxes    = (const float*)d_in[1];
    const float* scores   = (const float*)d_in[2];
    float* out = (float*)d_out;

    k1<<<NCLS, SORTN>>>(boxes, scores);
    k2f<<<NCLS * CSZ, 512>>>(boxes, pred_cls, out);
}

// round 11
// speedup vs baseline: 1.2318x; 1.2318x over previous
#include <cuda_runtime.h>
#include <math_constants.h>

#define NCLS   20
#define NBOX   400
#define SORTN  512
#define IMGW   1333.0f
#define IMGH   800.0f
#define TOPK   100
#define NSEL   (NCLS * TOPK)     // 2000
#define NW     13                // 400 bits -> 13 u32 words
#define SENTK  0xFFFFFFFFFFFFFFFFull
#define FULLM  0xFFFFFFFFu

// ---------------- device scratch ----------------
__device__ unsigned long long g_skey[NCLS * SORTN];   // sorted keys per class
__device__ float4             g_sbox[NCLS * NBOX];    // clipped boxes in sorted order
__device__ int                g_m[NCLS];              // valid count per class
__device__ unsigned int       g_mask[NCLS * NBOX * NW];
__device__ unsigned long long g_selkey[NSEL];         // per class: sorted kept top-100 (pad)
__device__ unsigned int       g_maxBits = 0u;
__device__ unsigned int       g_done    = 0u;
__device__ unsigned int       g_done2   = 0u;

// descending-sortable mapping (ascending u64 sort -> descending float score)
__device__ __forceinline__ unsigned int ord_desc(float f) {
    unsigned int u = __float_as_uint(f);
    unsigned int m = (u & 0x80000000u) ? ~u : (u | 0x80000000u);
    return ~m;
}
__device__ __forceinline__ float inv_ord(unsigned int o) {
    unsigned int m = ~o;
    unsigned int u = (m & 0x80000000u) ? (m & 0x7FFFFFFFu) : ~m;
    return __uint_as_float(u);
}
__device__ __forceinline__ unsigned long long shfl_xor_u64(unsigned long long v, int jj) {
    unsigned int lo = (unsigned int)v, hi = (unsigned int)(v >> 32);
    lo = __shfl_xor_sync(FULLM, lo, jj);
    hi = __shfl_xor_sync(FULLM, hi, jj);
    return ((unsigned long long)hi << 32) | lo;
}
__device__ __forceinline__ unsigned long long uminll(unsigned long long a, unsigned long long b) { return a < b ? a : b; }
__device__ __forceinline__ unsigned long long umaxll(unsigned long long a, unsigned long long b) { return a > b ? a : b; }

// ---------------- k1: per-class load/clip/key + double-buffered hybrid bitonic sort ------
__global__ void __launch_bounds__(SORTN) k1(const float* __restrict__ boxes,
                                            const float* __restrict__ scores,
                                            float* __restrict__ out) {
    __shared__ unsigned long long sbuf[2][SORTN];   // ping-pong: 1 barrier per smem stage
    __shared__ float4       s_cbox[NBOX];
    __shared__ unsigned int s_wmax[16];

    const int cls = blockIdx.x, tid = threadIdx.x, lane = tid & 31;

    // class-0 block pre-writes all default output rows (off critical path)
    if (cls == 0) {
        if (tid < 4 * TOPK) out[tid] = 0.0f;                  // boxes
        if (tid >= 512 - TOPK) {                              // scores/cls/valid by last 100 thr
            int r = tid - (512 - TOPK);
            out[4 * TOPK + r] = 0.0f;
            out[5 * TOPK + r] = -1.0f;
            out[6 * TOPK + r] = 0.0f;
        }
    }

    float lmax = 0.0f;
    bool  valid = false;
    unsigned long long v = SENTK;
    if (tid < NBOX) {
        float4 bx = reinterpret_cast<const float4*>(boxes)[cls * NBOX + tid];
        float2 sc = reinterpret_cast<const float2*>(scores)[cls * NBOX + tid];
        bool fin = isfinite(bx.x) && isfinite(bx.y) && isfinite(bx.z) && isfinite(bx.w)
                && isfinite(sc.x) && isfinite(sc.y);
        float x1 = fminf(fmaxf(bx.x, 0.0f), IMGW);
        float y1 = fminf(fmaxf(bx.y, 0.0f), IMGH);
        float x2 = fminf(fmaxf(bx.z, 0.0f), IMGW);
        float y2 = fminf(fmaxf(bx.w, 0.0f), IMGH);
        valid = fin && (sc.x > 0.05f);
        float masked = valid ? sc.x : -CUDART_INF_F;
        unsigned int j = (unsigned int)(tid * NCLS + cls);    // transposed index
        v = ((unsigned long long)ord_desc(masked) << 32) | j;
        s_cbox[tid] = make_float4(x1, y1, x2, y2);
        lmax = fmaxf(fmaxf(x1, x2), fmaxf(y1, y2));
    }
    unsigned int wb = __reduce_max_sync(FULLM, __float_as_uint(lmax));
    if (lane == 0) s_wmax[tid >> 5] = wb;
    const int m = __syncthreads_count(valid);
    if (tid == 0) {
        unsigned int mx = 0;
        #pragma unroll
        for (int w = 0; w < 16; w++) mx = max(mx, s_wmax[w]);
        atomicMax(&g_maxBits, mx);
    }

    // hybrid bitonic sort: ping-pong smem stages jj>=32 (1 barrier each), shfl jj<=16
    int pb = 0;
    for (int k = 2; k <= SORTN; k <<= 1) {
        for (int jj = k >> 1; jj >= 32; jj >>= 1) {
            sbuf[pb][tid] = v;
            __syncthreads();
            unsigned long long p = sbuf[pb][tid ^ jj];
            pb ^= 1;
            bool km = (((tid & k) == 0) == ((tid & jj) == 0));
            v = km ? uminll(v, p) : umaxll(v, p);
        }
        int j0 = (k >> 1) < 16 ? (k >> 1) : 16;
        for (int jj = j0; jj >= 1; jj >>= 1) {
            unsigned long long p = shfl_xor_u64(v, jj);
            bool km = (((tid & k) == 0) == ((tid & jj) == 0));
            v = km ? uminll(v, p) : umaxll(v, p);
        }
    }

    g_skey[cls * SORTN + tid] = v;
    if (tid < m) {
        unsigned int j = (unsigned int)v;
        int b = (int)(j / NCLS);
        g_sbox[cls * NBOX + tid] = s_cbox[b];
    }
    if (tid == 0) g_m[cls] = m;
}

// ---------------- k2: mask matrix, 520 blocks (class x 16-row tile), half-word split -----
__global__ void __launch_bounds__(512) k2() {
    __shared__ float4 s_b[NBOX];
    __shared__ float  s_a[NBOX];

    const int c = blockIdx.y, ty = blockIdx.x;     // ty in 0..25: rows [16ty, 16ty+16)
    const int tid = threadIdx.x;
    const int m = g_m[c];

    const float offv  = __fadd_rn(__uint_as_float(g_maxBits), 1.0f);
    const float shift = __fmul_rn((float)c, offv);

    for (int t = tid; t < m; t += 512) {
        float4 bx = g_sbox[c * NBOX + t];
        float4 sb = make_float4(__fadd_rn(bx.x, shift), __fadd_rn(bx.y, shift),
                                __fadd_rn(bx.z, shift), __fadd_rn(bx.w, shift));
        s_b[t] = sb;
        s_a[t] = __fmul_rn(__fsub_rn(sb.z, sb.x), __fsub_rn(sb.w, sb.y));
    }
    __syncthreads();

    // task map: tid in [0,416): i_local = tid/26, rem = tid%26, w = rem/2, h = rem%2
    // adjacent threads (2k, 2k+1) share (i, w) and split the word into 16-col halves.
    if (tid < 416) {                               // warps 0..12 fully active
        const int il  = tid / 26;
        const int rem = tid - il * 26;
        const int w   = rem >> 1;
        const int h   = rem & 1;
        const int i   = ty * 16 + il;

        unsigned int bits = 0;
        if (i < m) {
            const int lo = w * 32 + h * 16;
            const int hi = min(m, lo + 16);
            const int st = max(lo, i + 1);
            if (st < hi) {
                float4 bi = s_b[i];
                float  ai = s_a[i];
                for (int jd = st; jd < hi; jd++) {
                    float4 bj = s_b[jd];
                    float iw = fmaxf(__fsub_rn(fminf(bi.z, bj.z), fmaxf(bi.x, bj.x)), 0.0f);
                    float ih = fmaxf(__fsub_rn(fminf(bi.w, bj.w), fmaxf(bi.y, bj.y)), 0.0f);
                    float inter = __fmul_rn(iw, ih);
                    float uni = __fsub_rn(__fadd_rn(ai, s_a[jd]), inter);
                    float iou = (uni > 0.0f) ? __fdiv_rn(inter, uni) : 0.0f;
                    if (iou > 0.5f) bits |= 1u << (jd - w * 32);
                }
            }
        }
        bits |= __shfl_xor_sync(FULLM, bits, 1);   // merge the two 16-col halves
        if (h == 0 && i < m) g_mask[(c * NBOX + i) * NW + w] = bits;
    }
}

// ---------------- k34: greedy scan + rendezvous + merge-by-rank + output ----------------
__global__ void __launch_bounds__(512) k34(const float* __restrict__ boxes,
                                           const int* __restrict__ pred_cls,
                                           float* __restrict__ out) {
    __shared__ __align__(16) unsigned int       s_mask[NBOX * NW];  // 20.8 KB
    __shared__ __align__(16) unsigned long long s_sel[NSEL];        // 16 KB
    __shared__ unsigned long long s_skey[SORTN];                    // 4 KB

    const int c = blockIdx.x, tid = threadIdx.x, lane = tid & 31;
    const int m = g_m[c];

    // stage mask + own sorted keys into smem (512 threads, high MLP)
    for (int t = tid; t < m * NW; t += 512) s_mask[t] = g_mask[c * NBOX * NW + t];
    for (int t = tid; t < SORTN; t += 512)  s_skey[t] = g_skey[c * SORTN + t];
    __syncthreads();

    // greedy scan (warp 0, register-batched) + emit kept top-100 to global
    if (tid < 32) {
        unsigned int mysup = 0;                // lane w owns rows [32w, 32w+32)
        const int nb = (m + 31) >> 5;
        for (int b = 0; b < nb; b++) {
            unsigned int cur = __shfl_sync(FULLM, mysup, b);
            const int base = b << 5;
            const int rows = min(32, m - base);
            unsigned int wreg[32];
            #pragma unroll
            for (int q = 0; q < 32; q++)
                wreg[q] = (q < rows) ? s_mask[(base + q) * NW + b] : 0u;
            #pragma unroll
            for (int q = 0; q < 32; q++) {
                if (q < rows && !((cur >> q) & 1u)) {
                    cur |= wreg[q];
                    if (lane < NW) mysup |= s_mask[(base + q) * NW + lane];
                }
            }
        }
        int cnt = 0;
        for (int bs = 0; bs < m; bs += 32) {
            int t = bs + lane;
            unsigned int supw = __shfl_sync(FULLM, mysup, t >> 5);
            bool kept = (t < m) && !((supw >> (t & 31)) & 1u);
            unsigned int bal = __ballot_sync(FULLM, kept);
            int pos = cnt + __popc(bal & ((1u << lane) - 1u));
            if (kept && pos < TOPK) g_selkey[c * TOPK + pos] = s_skey[t];
            cnt += __popc(bal);
        }
        cnt = min(cnt, TOPK);
        for (int p = cnt + lane; p < TOPK; p += 32) g_selkey[c * TOPK + p] = SENTK;
        __threadfence();                       // publish selkey stores
        __syncwarp();
        if (lane == 0) atomicAdd(&g_done, 1u);
    }
    __syncthreads();

    // rendezvous: all 20 classes' selkey visible (identical code -> tiny skew)
    if (tid == 0) {
        volatile unsigned int* vd = &g_done;
        while (*vd < (unsigned)NCLS) { }
        __threadfence();
    }
    __syncthreads();

    // load all 2000 candidates (512 threads -> 4 loads each, high MLP)
    for (int t = tid; t < NSEL; t += 512) s_sel[t] = g_selkey[t];
    __syncthreads();

    // merge-by-rank: rank own class's kept keys against the other 19 sorted lists
    if (tid < TOPK) {
        unsigned long long e = s_sel[c * TOPK + tid];
        if (e != SENTK) {
            int rank = tid;                    // position within own sorted list
            #pragma unroll
            for (int c2 = 0; c2 < NCLS; c2++) {
                if (c2 == c) continue;
                const unsigned long long* seg = s_sel + c2 * TOPK;
                int lo = 0;                    // lower_bound: #elements < e
                #pragma unroll
                for (int s = 64; s > 0; s >>= 1) {
                    int p = lo + s;
                    if (p <= TOPK && seg[p - 1] < e) lo = p;
                }
                rank += lo;
            }
            if (rank < TOPK) {
                unsigned int j = (unsigned int)e;
                int cc = (int)(j % NCLS);
                int b  = (int)(j / NCLS);
                int i  = cc * NBOX + b;
                float4 bx = reinterpret_cast<const float4*>(boxes)[i];
                out[rank * 4 + 0] = fminf(fmaxf(bx.x, 0.0f), IMGW);
                out[rank * 4 + 1] = fminf(fmaxf(bx.y, 0.0f), IMGH);
                out[rank * 4 + 2] = fminf(fmaxf(bx.z, 0.0f), IMGW);
                out[rank * 4 + 3] = fminf(fmaxf(bx.w, 0.0f), IMGH);
                out[4 * TOPK + rank] = inv_ord((unsigned int)(e >> 32));
                out[5 * TOPK + rank] = (float)pred_cls[i];
                out[6 * TOPK + rank] = 1.0f;
            }
        }
    }

    // last finisher resets globals for the next graph replay
    __syncthreads();
    if (tid == 0) {
        unsigned int r2 = atomicAdd(&g_done2, 1u);
        if (r2 == NCLS - 1) {
            g_maxBits = 0u;
            g_done    = 0u;
            g_done2   = 0u;
            __threadfence();
        }
    }
}

// ---------------- launch ----------------
extern "C" void kernel_launch(void* const* d_in, const int* in_sizes, int n_in,
                              void* d_out, int out_size) {
    const int*   pred_cls = (const int*)d_in[0];
    const float* boxes    = (const float*)d_in[1];
    const float* scores   = (const float*)d_in[2];
    float* out = (float*)d_out;

    k1<<<NCLS, SORTN>>>(boxes, scores, out);
    k2<<<dim3(26, NCLS), 512>>>();
    k34<<<NCLS, 512>>>(boxes, pred_cls, out);
}

// round 12
// speedup vs baseline: 1.3584x; 1.1028x over previous
#include <cuda_runtime.h>
#include <math_constants.h>

#define NCLS   20
#define NBOX   400
#define SORTN  512
#define IMGW   1333.0f
#define IMGH   800.0f
#define TOPK   100
#define NSEL   (NCLS * TOPK)     // 2000
#define NW     13                // 400 bits -> 13 u32 words
#define NTILE  13                // 13 x 32 rows = 416 >= 400
#define SENTK  0xFFFFFFFFFFFFFFFFull
#define FULLM  0xFFFFFFFFu

// ---------------- device scratch ----------------
__device__ unsigned long long g_skey[NCLS * SORTN];   // sorted keys per class
__device__ float4             g_sbox[NCLS * NBOX];    // clipped boxes in sorted order
__device__ int                g_m[NCLS];              // valid count per class
__device__ unsigned int       g_mask[NCLS * NBOX * NW];
__device__ unsigned long long g_selkey[NSEL];         // per class: sorted kept top-100 (pad)
__device__ unsigned int       g_maxBits = 0u;
__device__ unsigned int       g_tile[NCLS];           // mask-tile completion counters
__device__ unsigned int       g_T       = 0u;
__device__ unsigned int       g_done    = 0u;
__device__ unsigned int       g_done2   = 0u;

// descending-sortable mapping (ascending u64 sort -> descending float score)
__device__ __forceinline__ unsigned int ord_desc(float f) {
    unsigned int u = __float_as_uint(f);
    unsigned int m = (u & 0x80000000u) ? ~u : (u | 0x80000000u);
    return ~m;
}
__device__ __forceinline__ float inv_ord(unsigned int o) {
    unsigned int m = ~o;
    unsigned int u = (m & 0x80000000u) ? (m & 0x7FFFFFFFu) : ~m;
    return __uint_as_float(u);
}
__device__ __forceinline__ unsigned long long shfl_xor_u64(unsigned long long v, int jj) {
    unsigned int lo = (unsigned int)v, hi = (unsigned int)(v >> 32);
    lo = __shfl_xor_sync(FULLM, lo, jj);
    hi = __shfl_xor_sync(FULLM, hi, jj);
    return ((unsigned long long)hi << 32) | lo;
}
__device__ __forceinline__ unsigned long long uminll(unsigned long long a, unsigned long long b) { return a < b ? a : b; }
__device__ __forceinline__ unsigned long long umaxll(unsigned long long a, unsigned long long b) { return a > b ? a : b; }

// ---------------- k1: per-class load/clip/key + hybrid bitonic sort (R9 verbatim) --------
__global__ void __launch_bounds__(SORTN) k1(const float* __restrict__ boxes,
                                            const float* __restrict__ scores) {
    __shared__ unsigned long long skey[SORTN];
    __shared__ float4       s_cbox[NBOX];
    __shared__ unsigned int s_wmax[16];

    const int cls = blockIdx.x, tid = threadIdx.x, lane = tid & 31;

    float lmax = 0.0f;
    bool  valid = false;
    unsigned long long v = SENTK;
    if (tid < NBOX) {
        float4 bx = reinterpret_cast<const float4*>(boxes)[cls * NBOX + tid];
        float2 sc = reinterpret_cast<const float2*>(scores)[cls * NBOX + tid];
        bool fin = isfinite(bx.x) && isfinite(bx.y) && isfinite(bx.z) && isfinite(bx.w)
                && isfinite(sc.x) && isfinite(sc.y);
        float x1 = fminf(fmaxf(bx.x, 0.0f), IMGW);
        float y1 = fminf(fmaxf(bx.y, 0.0f), IMGH);
        float x2 = fminf(fmaxf(bx.z, 0.0f), IMGW);
        float y2 = fminf(fmaxf(bx.w, 0.0f), IMGH);
        valid = fin && (sc.x > 0.05f);
        float masked = valid ? sc.x : -CUDART_INF_F;
        unsigned int j = (unsigned int)(tid * NCLS + cls);       // transposed index
        v = ((unsigned long long)ord_desc(masked) << 32) | j;
        s_cbox[tid] = make_float4(x1, y1, x2, y2);
        lmax = fmaxf(fmaxf(x1, x2), fmaxf(y1, y2));
    }
    unsigned int wb = __reduce_max_sync(FULLM, __float_as_uint(lmax));
    if (lane == 0) s_wmax[tid >> 5] = wb;
    const int m = __syncthreads_count(valid);
    if (tid == 0) {
        unsigned int mx = 0;
        #pragma unroll
        for (int w = 0; w < 16; w++) mx = max(mx, s_wmax[w]);
        atomicMax(&g_maxBits, mx);
    }

    // hybrid bitonic sort: smem stages jj>=32, shfl stages jj<=16
    for (int k = 2; k <= SORTN; k <<= 1) {
        for (int jj = k >> 1; jj >= 32; jj >>= 1) {
            skey[tid] = v;
            __syncthreads();
            unsigned long long p = skey[tid ^ jj];
            bool km = (((tid & k) == 0) == ((tid & jj) == 0));
            v = km ? uminll(v, p) : umaxll(v, p);
            __syncthreads();
        }
        int j0 = (k >> 1) < 16 ? (k >> 1) : 16;
        for (int jj = j0; jj >= 1; jj >>= 1) {
            unsigned long long p = shfl_xor_u64(v, jj);
            bool km = (((tid & k) == 0) == ((tid & jj) == 0));
            v = km ? uminll(v, p) : umaxll(v, p);
        }
    }

    g_skey[cls * SORTN + tid] = v;
    if (tid < m) {
        unsigned int j = (unsigned int)v;
        int b = (int)(j / NCLS);
        g_sbox[cls * NBOX + tid] = s_cbox[b];
    }
    if (tid == 0) g_m[cls] = m;
}

// ---------------- kB: mask tile + last-tile election -> greedy + merge + output ----------
__global__ void __launch_bounds__(512) kB(const float* __restrict__ boxes,
                                          const int* __restrict__ pred_cls,
                                          float* __restrict__ out) {
    // buf1: s_b+s_a during mask phase; s_mask for elected block (they never overlap in time)
    __shared__ __align__(16) unsigned char buf1[NBOX * NW * 4];     // 20.8 KB
    __shared__ __align__(16) unsigned long long s_sel[NSEL];        // 16 KB (elected only)
    __shared__ unsigned long long s_skey[SORTN];                    // 4 KB (elected only)
    __shared__ int s_elect, s_T;

    float4*       s_b    = reinterpret_cast<float4*>(buf1);                    // [NBOX]
    float*        s_a    = reinterpret_cast<float*>(buf1 + NBOX * 16);         // [NBOX]
    unsigned int* s_mask = reinterpret_cast<unsigned int*>(buf1);              // [NBOX*NW]

    const int c   = blockIdx.y;                    // class
    const int ty  = blockIdx.x;                    // 32-row tile 0..12
    const int tid = threadIdx.x;
    const int wd  = tid >> 5, lane = tid & 31;
    const int m   = g_m[c];

    const float offv  = __fadd_rn(__uint_as_float(g_maxBits), 1.0f);
    const float shift = __fmul_rn((float)c, offv);

    // stage shifted boxes + areas (512 threads)
    for (int t = tid; t < m; t += 512) {
        float4 bx = g_sbox[c * NBOX + t];
        float4 sb = make_float4(__fadd_rn(bx.x, shift), __fadd_rn(bx.y, shift),
                                __fadd_rn(bx.z, shift), __fadd_rn(bx.w, shift));
        s_b[t] = sb;
        s_a[t] = __fmul_rn(__fsub_rn(sb.z, sb.x), __fsub_rn(sb.w, sb.y));
    }
    __syncthreads();

    // this block's 32-row mask tile (warps 0..12 carry words 0..12)
    {
        const int i = ty * 32 + lane;
        if (wd < NW && i < m) {
            unsigned int bits = 0;
            const int lo = wd * 32;
            const int hi = min(m, lo + 32);
            const int st = max(lo, i + 1);
            if (st < hi) {
                float4 bi = s_b[i];
                float  ai = s_a[i];
                for (int jd = st; jd < hi; jd++) {
                    float4 bj = s_b[jd];
                    float iw = fmaxf(__fsub_rn(fminf(bi.z, bj.z), fmaxf(bi.x, bj.x)), 0.0f);
                    float ih = fmaxf(__fsub_rn(fminf(bi.w, bj.w), fmaxf(bi.y, bj.y)), 0.0f);
                    float inter = __fmul_rn(iw, ih);
                    float uni = __fsub_rn(__fadd_rn(ai, s_a[jd]), inter);
                    float iou = (uni > 0.0f) ? __fdiv_rn(inter, uni) : 0.0f;
                    if (iou > 0.5f) bits |= 1u << (jd - lo);
                }
            }
            g_mask[(c * NBOX + i) * NW + wd] = bits;
        }
    }
    __threadfence();                               // release mask stores
    __syncthreads();
    if (tid == 0) {
        unsigned int r = atomicAdd(&g_tile[c], 1u);
        s_elect = (r == NTILE - 1) ? 1 : 0;        // last tile of this class proceeds
    }
    __syncthreads();
    if (!s_elect) return;

    // ================= elected block (one per class) =================
    __threadfence();                               // acquire peers' mask stores
    for (int t = tid; t < m * NW; t += 512) s_mask[t] = g_mask[c * NBOX * NW + t];
    for (int t = tid; t < SORTN; t += 512)  s_skey[t] = g_skey[c * SORTN + t];
    __syncthreads();

    // greedy scan (warp 0, register-batched) + emit kept top-100 to global
    if (tid < 32) {
        unsigned int mysup = 0;                    // lane w owns rows [32w, 32w+32)
        const int nb = (m + 31) >> 5;
        for (int b = 0; b < nb; b++) {
            unsigned int cur = __shfl_sync(FULLM, mysup, b);
            const int base = b << 5;
            const int rows = min(32, m - base);
            unsigned int wreg[32];
            #pragma unroll
            for (int q = 0; q < 32; q++)
                wreg[q] = (q < rows) ? s_mask[(base + q) * NW + b] : 0u;
            #pragma unroll
            for (int q = 0; q < 32; q++) {
                if (q < rows && !((cur >> q) & 1u)) {
                    cur |= wreg[q];
                    if (lane < NW) mysup |= s_mask[(base + q) * NW + lane];
                }
            }
        }
        int cnt = 0;
        for (int bs = 0; bs < m; bs += 32) {
            int t = bs + lane;
            unsigned int supw = __shfl_sync(FULLM, mysup, t >> 5);
            bool kept = (t < m) && !((supw >> (t & 31)) & 1u);
            unsigned int bal = __ballot_sync(FULLM, kept);
            int pos = cnt + __popc(bal & ((1u << lane) - 1u));
            if (kept && pos < TOPK) g_selkey[c * TOPK + pos] = s_skey[t];
            cnt += __popc(bal);
        }
        cnt = min(cnt, TOPK);
        for (int p = cnt + lane; p < TOPK; p += 32) g_selkey[c * TOPK + p] = SENTK;
        __threadfence();                           // publish selkey stores
        __syncwarp();
        if (lane == 0) {
            atomicAdd(&g_T, (unsigned int)cnt);
            __threadfence();
            atomicAdd(&g_done, 1u);
        }
    }
    __syncthreads();

    // rendezvous: all 20 classes' selkey visible (20 pollers only)
    if (tid == 0) {
        volatile unsigned int* vd = &g_done;
        while (*vd < (unsigned)NCLS) { }
        __threadfence();
        s_T = (int)*(volatile unsigned int*)&g_T;
    }
    __syncthreads();                               // s_mask dead below? (kept: s_sel separate)

    // load all 2000 candidates (512 threads -> 4 loads each, high MLP)
    for (int t = tid; t < NSEL; t += 512) s_sel[t] = g_selkey[t];
    __syncthreads();

    // class 0's elected block fills default rows [T, 100)
    if (c == 0) {
        for (int r = s_T + tid; r < TOPK; r += 512) {
            out[r * 4 + 0] = 0.0f;
            out[r * 4 + 1] = 0.0f;
            out[r * 4 + 2] = 0.0f;
            out[r * 4 + 3] = 0.0f;
            out[4 * TOPK + r] = 0.0f;
            out[5 * TOPK + r] = -1.0f;
            out[6 * TOPK + r] = 0.0f;
        }
    }

    // merge-by-rank: rank own class's kept keys against the other 19 sorted lists
    if (tid < TOPK) {
        unsigned long long e = s_sel[c * TOPK + tid];
        if (e != SENTK) {
            int rank = tid;                        // position within own sorted list
            #pragma unroll
            for (int c2 = 0; c2 < NCLS; c2++) {
                if (c2 == c) continue;
                const unsigned long long* seg = s_sel + c2 * TOPK;
                int lo = 0;                        // lower_bound: #elements < e
                #pragma unroll
                for (int s = 64; s > 0; s >>= 1) {
                    int p = lo + s;
                    if (p <= TOPK && seg[p - 1] < e) lo = p;
                }
                rank += lo;
            }
            if (rank < TOPK) {
                unsigned int j = (unsigned int)e;
                int cc = (int)(j % NCLS);
                int b  = (int)(j / NCLS);
                int i  = cc * NBOX + b;
                float4 bx = reinterpret_cast<const float4*>(boxes)[i];
                out[rank * 4 + 0] = fminf(fmaxf(bx.x, 0.0f), IMGW);
                out[rank * 4 + 1] = fminf(fmaxf(bx.y, 0.0f), IMGH);
                out[rank * 4 + 2] = fminf(fmaxf(bx.z, 0.0f), IMGW);
                out[rank * 4 + 3] = fminf(fmaxf(bx.w, 0.0f), IMGH);
                out[4 * TOPK + rank] = inv_ord((unsigned int)(e >> 32));
                out[5 * TOPK + rank] = (float)pred_cls[i];
                out[6 * TOPK + rank] = 1.0f;
            }
        }
    }

    // last finisher resets globals for the next graph replay
    __syncthreads();
    if (tid == 0) {
        unsigned int r2 = atomicAdd(&g_done2, 1u);
        if (r2 == NCLS - 1) {
            g_maxBits = 0u;
            g_T       = 0u;
            g_done    = 0u;
            g_done2   = 0u;
            #pragma unroll
            for (int c2 = 0; c2 < NCLS; c2++) g_tile[c2] = 0u;
            __threadfence();
        }
    }
}

// ---------------- launch ----------------
extern "C" void kernel_launch(void* const* d_in, const int* in_sizes, int n_in,
                              void* d_out, int out_size) {
    const int*   pred_cls = (const int*)d_in[0];
    const float* boxes    = (const float*)d_in[1];
    const float* scores   = (const float*)d_in[2];
    float* out = (float*)d_out;

    k1<<<NCLS, SORTN>>>(boxes, scores);
    kB<<<dim3(NTILE, NCLS), 512>>>(boxes, pred_cls, out);
}

// round 13
// speedup vs baseline: 1.5454x; 1.1377x over previous
#include <cuda_runtime.h>
#include <math_constants.h>

#define NCLS   20
#define NBOX   400
#define SORTN  512
#define IMGW   1333.0f
#define IMGH   800.0f
#define TOPK   100
#define NSEL   (NCLS * TOPK)     // 2000
#define NW     13                // 400 bits -> 13 u32 words
#define NTILE  13                // 13 x 32 rows = 416 >= 400
#define SENTK  0xFFFFFFFFFFFFFFFFull
#define FULLM  0xFFFFFFFFu

// ---------------- device scratch ----------------
__device__ unsigned long long g_skey[NCLS * SORTN];   // sorted keys per class
__device__ float4             g_sbox[NCLS * NBOX];    // clipped boxes in sorted order
__device__ int                g_m[NCLS];              // valid count per class
__device__ unsigned int       g_mask[NCLS * NW * NBOX]; // [class][word][row] -> coalesced
__device__ unsigned long long g_selkey[NSEL];         // per class: sorted kept top-100 (pad)
__device__ unsigned int       g_maxBits = 0u;
__device__ unsigned int       g_tile[NCLS];           // mask-tile completion counters
__device__ unsigned int       g_done    = 0u;
__device__ unsigned int       g_done2   = 0u;

// descending-sortable mapping (ascending u64 sort -> descending float score)
__device__ __forceinline__ unsigned int ord_desc(float f) {
    unsigned int u = __float_as_uint(f);
    unsigned int m = (u & 0x80000000u) ? ~u : (u | 0x80000000u);
    return ~m;
}
__device__ __forceinline__ float inv_ord(unsigned int o) {
    unsigned int m = ~o;
    unsigned int u = (m & 0x80000000u) ? (m & 0x7FFFFFFFu) : ~m;
    return __uint_as_float(u);
}
__device__ __forceinline__ unsigned long long shfl_xor_u64(unsigned long long v, int jj) {
    unsigned int lo = (unsigned int)v, hi = (unsigned int)(v >> 32);
    lo = __shfl_xor_sync(FULLM, lo, jj);
    hi = __shfl_xor_sync(FULLM, hi, jj);
    return ((unsigned long long)hi << 32) | lo;
}
__device__ __forceinline__ unsigned long long uminll(unsigned long long a, unsigned long long b) { return a < b ? a : b; }
__device__ __forceinline__ unsigned long long umaxll(unsigned long long a, unsigned long long b) { return a > b ? a : b; }

// ---------------- k1: per-class load/clip/key + hybrid bitonic sort ----------------
__global__ void __launch_bounds__(SORTN) k1(const float* __restrict__ boxes,
                                            const float* __restrict__ scores,
                                            float* __restrict__ out) {
    __shared__ unsigned long long skey[SORTN];
    __shared__ float4       s_cbox[NBOX];
    __shared__ unsigned int s_wmax[16];

    const int cls = blockIdx.x, tid = threadIdx.x, lane = tid & 31;

    float lmax = 0.0f;
    bool  valid = false;
    unsigned long long v = SENTK;
    if (tid < NBOX) {
        float4 bx = reinterpret_cast<const float4*>(boxes)[cls * NBOX + tid];
        float2 sc = reinterpret_cast<const float2*>(scores)[cls * NBOX + tid];
        bool fin = isfinite(bx.x) && isfinite(bx.y) && isfinite(bx.z) && isfinite(bx.w)
                && isfinite(sc.x) && isfinite(sc.y);
        float x1 = fminf(fmaxf(bx.x, 0.0f), IMGW);
        float y1 = fminf(fmaxf(bx.y, 0.0f), IMGH);
        float x2 = fminf(fmaxf(bx.z, 0.0f), IMGW);
        float y2 = fminf(fmaxf(bx.w, 0.0f), IMGH);
        valid = fin && (sc.x > 0.05f);
        float masked = valid ? sc.x : -CUDART_INF_F;
        unsigned int j = (unsigned int)(tid * NCLS + cls);       // transposed index
        v = ((unsigned long long)ord_desc(masked) << 32) | j;
        s_cbox[tid] = make_float4(x1, y1, x2, y2);
        lmax = fmaxf(fmaxf(x1, x2), fmaxf(y1, y2));
    }
    unsigned int wb = __reduce_max_sync(FULLM, __float_as_uint(lmax));
    if (lane == 0) s_wmax[tid >> 5] = wb;
    const int m = __syncthreads_count(valid);
    if (tid == 0) {
        unsigned int mx = 0;
        #pragma unroll
        for (int w = 0; w < 16; w++) mx = max(mx, s_wmax[w]);
        atomicMax(&g_maxBits, mx);
    }

    // hybrid bitonic sort: smem stages jj>=32, shfl stages jj<=16
    for (int k = 2; k <= SORTN; k <<= 1) {
        for (int jj = k >> 1; jj >= 32; jj >>= 1) {
            skey[tid] = v;
            __syncthreads();
            unsigned long long p = skey[tid ^ jj];
            bool km = (((tid & k) == 0) == ((tid & jj) == 0));
            v = km ? uminll(v, p) : umaxll(v, p);
            __syncthreads();
        }
        int j0 = (k >> 1) < 16 ? (k >> 1) : 16;
        for (int jj = j0; jj >= 1; jj >>= 1) {
            unsigned long long p = shfl_xor_u64(v, jj);
            bool km = (((tid & k) == 0) == ((tid & jj) == 0));
            v = km ? uminll(v, p) : umaxll(v, p);
        }
    }

    g_skey[cls * SORTN + tid] = v;
    if (tid < m) {
        unsigned int j = (unsigned int)v;
        int b = (int)(j / NCLS);
        g_sbox[cls * NBOX + tid] = s_cbox[b];
    }
    if (tid == 0) g_m[cls] = m;

    // class-0 block pre-writes ALL default output rows; kB overwrites ranked rows
    if (cls == 0) {
        if (tid < 4 * TOPK) out[tid] = 0.0f;                  // boxes
        if (tid < TOPK) {
            out[4 * TOPK + tid] = 0.0f;                       // scores
            out[5 * TOPK + tid] = -1.0f;                      // cls
            out[6 * TOPK + tid] = 0.0f;                       // valid
        }
    }
}

// ---------------- kB: mask tile + last-tile election -> greedy + merge + output ----------
__global__ void __launch_bounds__(512) kB(const float* __restrict__ boxes,
                                          const int* __restrict__ pred_cls,
                                          float* __restrict__ out) {
    // buf1: s_b+s_a during mask phase; s_mask for elected block (disjoint in time)
    __shared__ __align__(16) unsigned char buf1[NBOX * NW * 4];     // 20.8 KB
    __shared__ __align__(16) unsigned long long s_sel[NSEL];        // 16 KB (elected only)
    __shared__ unsigned long long s_skey[SORTN];                    // 4 KB (elected only)
    __shared__ int s_elect;

    float4*       s_b    = reinterpret_cast<float4*>(buf1);                    // [NBOX]
    float*        s_a    = reinterpret_cast<float*>(buf1 + NBOX * 16);         // [NBOX]
    unsigned int* s_mask = reinterpret_cast<unsigned int*>(buf1);              // [NBOX*NW] row-major

    const int c   = blockIdx.y;                    // class
    const int ty  = blockIdx.x;                    // 32-row tile 0..12
    const int tid = threadIdx.x;
    const int wd  = tid >> 5, lane = tid & 31;
    const int m   = g_m[c];

    const float offv  = __fadd_rn(__uint_as_float(g_maxBits), 1.0f);
    const float shift = __fmul_rn((float)c, offv);

    // stage shifted boxes + areas (512 threads)
    for (int t = tid; t < m; t += 512) {
        float4 bx = g_sbox[c * NBOX + t];
        float4 sb = make_float4(__fadd_rn(bx.x, shift), __fadd_rn(bx.y, shift),
                                __fadd_rn(bx.z, shift), __fadd_rn(bx.w, shift));
        s_b[t] = sb;
        s_a[t] = __fmul_rn(__fsub_rn(sb.z, sb.x), __fsub_rn(sb.w, sb.y));
    }
    __syncthreads();

    // this block's 32-row mask tile (warps 0..12 carry words 0..12)
    // decision "iou > 0.5" computed division-free: uni>0 && inter > 0.5*uni
    {
        const int i = ty * 32 + lane;
        if (wd < NW && i < m) {
            unsigned int bits = 0;
            const int lo = wd * 32;
            const int hi = min(m, lo + 32);
            const int st = max(lo, i + 1);
            if (st < hi) {
                float4 bi = s_b[i];
                float  ai = s_a[i];
                #pragma unroll 4
                for (int jd = st; jd < hi; jd++) {
                    float4 bj = s_b[jd];
                    float iw = fmaxf(__fsub_rn(fminf(bi.z, bj.z), fmaxf(bi.x, bj.x)), 0.0f);
                    float ih = fmaxf(__fsub_rn(fminf(bi.w, bj.w), fmaxf(bi.y, bj.y)), 0.0f);
                    float inter = __fmul_rn(iw, ih);
                    float uni = __fsub_rn(__fadd_rn(ai, s_a[jd]), inter);
                    if (uni > 0.0f && inter > __fmul_rn(0.5f, uni)) bits |= 1u << (jd - lo);
                }
            }
            g_mask[(c * NW + wd) * NBOX + i] = bits;   // coalesced (lane = row)
        }
    }
    __threadfence();                               // release mask stores
    __syncthreads();
    if (tid == 0) {
        unsigned int r = atomicAdd(&g_tile[c], 1u);
        s_elect = (r == NTILE - 1) ? 1 : 0;        // last tile of this class proceeds
    }
    __syncthreads();
    if (!s_elect) return;

    // ================= elected block (one per class) =================
    __threadfence();                               // acquire peers' mask stores
    // reload transposed: read coalesced [w][i], write smem row-major (stride-13: conflict-free)
    for (int t = tid; t < NW * NBOX; t += 512) {
        int w = t / NBOX;
        int i = t - w * NBOX;
        if (i < m) s_mask[i * NW + w] = g_mask[(c * NW + w) * NBOX + i];
    }
    for (int t = tid; t < SORTN; t += 512)  s_skey[t] = g_skey[c * SORTN + t];
    __syncthreads();

    // greedy scan (warp 0, register-batched) + emit kept top-100 to global
    if (tid < 32) {
        unsigned int mysup = 0;                    // lane w owns rows [32w, 32w+32)
        const int nb = (m + 31) >> 5;
        for (int b = 0; b < nb; b++) {
            unsigned int cur = __shfl_sync(FULLM, mysup, b);
            const int base = b << 5;
            const int rows = min(32, m - base);
            unsigned int wreg[32];
            #pragma unroll
            for (int q = 0; q < 32; q++)
                wreg[q] = (q < rows) ? s_mask[(base + q) * NW + b] : 0u;
            #pragma unroll
            for (int q = 0; q < 32; q++) {
                if (q < rows && !((cur >> q) & 1u)) {
                    cur |= wreg[q];
                    if (lane < NW) mysup |= s_mask[(base + q) * NW + lane];
                }
            }
        }
        int cnt = 0;
        for (int bs = 0; bs < m; bs += 32) {
            int t = bs + lane;
            unsigned int supw = __shfl_sync(FULLM, mysup, t >> 5);
            bool kept = (t < m) && !((supw >> (t & 31)) & 1u);
            unsigned int bal = __ballot_sync(FULLM, kept);
            int pos = cnt + __popc(bal & ((1u << lane) - 1u));
            if (kept && pos < TOPK) g_selkey[c * TOPK + pos] = s_skey[t];
            cnt += __popc(bal);
        }
        cnt = min(cnt, TOPK);
        for (int p = cnt + lane; p < TOPK; p += 32) g_selkey[c * TOPK + p] = SENTK;
        __threadfence();                           // publish selkey stores
        __syncwarp();
        if (lane == 0) atomicAdd(&g_done, 1u);
    }
    __syncthreads();

    // rendezvous: all 20 classes' selkey visible (20 pollers only)
    if (tid == 0) {
        volatile unsigned int* vd = &g_done;
        while (*vd < (unsigned)NCLS) { }
        __threadfence();
    }
    __syncthreads();

    // load all 2000 candidates (512 threads -> 4 loads each, high MLP)
    for (int t = tid; t < NSEL; t += 512) s_sel[t] = g_selkey[t];
    __syncthreads();

    // merge-by-rank: rank own class's kept keys against the other 19 sorted lists
    if (tid < TOPK) {
        unsigned long long e = s_sel[c * TOPK + tid];
        if (e != SENTK) {
            int rank = tid;                        // position within own sorted list
            #pragma unroll
            for (int c2 = 0; c2 < NCLS; c2++) {
                if (c2 == c) continue;
                const unsigned long long* seg = s_sel + c2 * TOPK;
                int lo = 0;                        // lower_bound: #elements < e
                #pragma unroll
                for (int s = 64; s > 0; s >>= 1) {
                    int p = lo + s;
                    if (p <= TOPK && seg[p - 1] < e) lo = p;
                }
                rank += lo;
            }
            if (rank < TOPK) {
                unsigned int j = (unsigned int)e;
                int cc = (int)(j % NCLS);
                int b  = (int)(j / NCLS);
                int i  = cc * NBOX + b;
                float4 bx = reinterpret_cast<const float4*>(boxes)[i];
                out[rank * 4 + 0] = fminf(fmaxf(bx.x, 0.0f), IMGW);
                out[rank * 4 + 1] = fminf(fmaxf(bx.y, 0.0f), IMGH);
                out[rank * 4 + 2] = fminf(fmaxf(bx.z, 0.0f), IMGW);
                out[rank * 4 + 3] = fminf(fmaxf(bx.w, 0.0f), IMGH);
                out[4 * TOPK + rank] = inv_ord((unsigned int)(e >> 32));
                out[5 * TOPK + rank] = (float)pred_cls[i];
                out[6 * TOPK + rank] = 1.0f;
            }
        }
    }

    // last finisher resets globals for the next graph replay
    __syncthreads();
    if (tid == 0) {
        unsigned int r2 = atomicAdd(&g_done2, 1u);
        if (r2 == NCLS - 1) {
            g_maxBits = 0u;
            g_done    = 0u;
            g_done2   = 0u;
            #pragma unroll
            for (int c2 = 0; c2 < NCLS; c2++) g_tile[c2] = 0u;
            __threadfence();
        }
    }
}

// ---------------- launch ----------------
extern "C" void kernel_launch(void* const* d_in, const int* in_sizes, int n_in,
                              void* d_out, int out_size) {
    const int*   pred_cls = (const int*)d_in[0];
    const float* boxes    = (const float*)d_in[1];
    const float* scores   = (const float*)d_in[2];
    float* out = (float*)d_out;

    k1<<<NCLS, SORTN>>>(boxes, scores, out);
    kB<<<dim3(NTILE, NCLS), 512>>>(boxes, pred_cls, out);
}

// round 14
// speedup vs baseline: 2.0840x; 1.3485x over previous
#include <cuda_runtime.h>
#include <math_constants.h>

#define NCLS   20
#define NBOX   400
#define SORTN  512
#define IMGW   1333.0f
#define IMGH   800.0f
#define TOPK   100
#define NSEL   (NCLS * TOPK)     // 2000
#define NW     13                // 400 bits -> 13 u32 words
#define NTILE  13                // 13 x 32 rows = 416 >= 400
#define SENTK  0xFFFFFFFFFFFFFFFFull
#define FULLM  0xFFFFFFFFu

// ---------------- device scratch ----------------
__device__ unsigned long long g_skey[NCLS * SORTN];   // sorted keys per class
__device__ float4             g_sbox[NCLS * NBOX];    // clipped boxes in sorted order
__device__ int                g_m[NCLS];              // valid count per class
__device__ unsigned int       g_mask[NCLS * NW * NBOX]; // [class][word][row] -> coalesced
__device__ unsigned long long g_selkey[NSEL];         // per class: sorted kept top-100 (pad)
__device__ unsigned int       g_maxBits = 0u;
__device__ unsigned int       g_tile[NCLS];           // mask-tile completion counters
__device__ unsigned int       g_done    = 0u;
__device__ unsigned int       g_done2   = 0u;

// descending-sortable mapping (ascending u64 sort -> descending float score)
__device__ __forceinline__ unsigned int ord_desc(float f) {
    unsigned int u = __float_as_uint(f);
    unsigned int m = (u & 0x80000000u) ? ~u : (u | 0x80000000u);
    return ~m;
}
__device__ __forceinline__ float inv_ord(unsigned int o) {
    unsigned int m = ~o;
    unsigned int u = (m & 0x80000000u) ? (m & 0x7FFFFFFFu) : ~m;
    return __uint_as_float(u);
}
__device__ __forceinline__ unsigned long long shfl_xor_u64(unsigned long long v, int jj) {
    unsigned int lo = (unsigned int)v, hi = (unsigned int)(v >> 32);
    lo = __shfl_xor_sync(FULLM, lo, jj);
    hi = __shfl_xor_sync(FULLM, hi, jj);
    return ((unsigned long long)hi << 32) | lo;
}
__device__ __forceinline__ unsigned long long uminll(unsigned long long a, unsigned long long b) { return a < b ? a : b; }
__device__ __forceinline__ unsigned long long umaxll(unsigned long long a, unsigned long long b) { return a > b ? a : b; }

// ---------------- k1: per-class load/clip/key + hybrid bitonic sort (R13 verbatim) -------
__global__ void __launch_bounds__(SORTN) k1(const float* __restrict__ boxes,
                                            const float* __restrict__ scores,
                                            float* __restrict__ out) {
    __shared__ unsigned long long skey[SORTN];
    __shared__ float4       s_cbox[NBOX];
    __shared__ unsigned int s_wmax[16];

    const int cls = blockIdx.x, tid = threadIdx.x, lane = tid & 31;

    float lmax = 0.0f;
    bool  valid = false;
    unsigned long long v = SENTK;
    if (tid < NBOX) {
        float4 bx = reinterpret_cast<const float4*>(boxes)[cls * NBOX + tid];
        float2 sc = reinterpret_cast<const float2*>(scores)[cls * NBOX + tid];
        bool fin = isfinite(bx.x) && isfinite(bx.y) && isfinite(bx.z) && isfinite(bx.w)
                && isfinite(sc.x) && isfinite(sc.y);
        float x1 = fminf(fmaxf(bx.x, 0.0f), IMGW);
        float y1 = fminf(fmaxf(bx.y, 0.0f), IMGH);
        float x2 = fminf(fmaxf(bx.z, 0.0f), IMGW);
        float y2 = fminf(fmaxf(bx.w, 0.0f), IMGH);
        valid = fin && (sc.x > 0.05f);
        float masked = valid ? sc.x : -CUDART_INF_F;
        unsigned int j = (unsigned int)(tid * NCLS + cls);       // transposed index
        v = ((unsigned long long)ord_desc(masked) << 32) | j;
        s_cbox[tid] = make_float4(x1, y1, x2, y2);
        lmax = fmaxf(fmaxf(x1, x2), fmaxf(y1, y2));
    }
    unsigned int wb = __reduce_max_sync(FULLM, __float_as_uint(lmax));
    if (lane == 0) s_wmax[tid >> 5] = wb;
    const int m = __syncthreads_count(valid);
    if (tid == 0) {
        unsigned int mx = 0;
        #pragma unroll
        for (int w = 0; w < 16; w++) mx = max(mx, s_wmax[w]);
        atomicMax(&g_maxBits, mx);
    }

    // hybrid bitonic sort: smem stages jj>=32, shfl stages jj<=16
    for (int k = 2; k <= SORTN; k <<= 1) {
        for (int jj = k >> 1; jj >= 32; jj >>= 1) {
            skey[tid] = v;
            __syncthreads();
            unsigned long long p = skey[tid ^ jj];
            bool km = (((tid & k) == 0) == ((tid & jj) == 0));
            v = km ? uminll(v, p) : umaxll(v, p);
            __syncthreads();
        }
        int j0 = (k >> 1) < 16 ? (k >> 1) : 16;
        for (int jj = j0; jj >= 1; jj >>= 1) {
            unsigned long long p = shfl_xor_u64(v, jj);
            bool km = (((tid & k) == 0) == ((tid & jj) == 0));
            v = km ? uminll(v, p) : umaxll(v, p);
        }
    }

    g_skey[cls * SORTN + tid] = v;
    if (tid < m) {
        unsigned int j = (unsigned int)v;
        int b = (int)(j / NCLS);
        g_sbox[cls * NBOX + tid] = s_cbox[b];
    }
    if (tid == 0) g_m[cls] = m;

    // class-0 block pre-writes ALL default output rows; kB overwrites ranked rows
    if (cls == 0) {
        if (tid < 4 * TOPK) out[tid] = 0.0f;                  // boxes
        if (tid < TOPK) {
            out[4 * TOPK + tid] = 0.0f;                       // scores
            out[5 * TOPK + tid] = -1.0f;                      // cls
            out[6 * TOPK + tid] = 0.0f;                       // valid
        }
    }
}

// ---------------- kB: mask tile + last-tile election -> greedy + merge + output ----------
__global__ void __launch_bounds__(512) kB(const float* __restrict__ boxes,
                                          const int* __restrict__ pred_cls,
                                          float* __restrict__ out) {
    // buf1: s_b+s_a during mask phase; s_mask for elected block (disjoint in time)
    __shared__ __align__(16) unsigned char buf1[NBOX * NW * 4];     // 20.8 KB
    __shared__ __align__(16) unsigned long long s_sel[NSEL];        // 16 KB (elected only)
    __shared__ unsigned long long s_skey[SORTN];                    // 4 KB (elected only)
    __shared__ int s_elect;

    float4*       s_b    = reinterpret_cast<float4*>(buf1);                    // [NBOX]
    float*        s_a    = reinterpret_cast<float*>(buf1 + NBOX * 16);         // [NBOX]
    unsigned int* s_mask = reinterpret_cast<unsigned int*>(buf1);              // [NBOX*NW] row-major

    const int c   = blockIdx.y;                    // class
    const int ty  = blockIdx.x;                    // 32-row tile 0..12
    const int tid = threadIdx.x;
    const int wd  = tid >> 5, lane = tid & 31;
    const int m   = g_m[c];                        // overlaps with staging below

    const float offv  = __fadd_rn(__uint_as_float(g_maxBits), 1.0f);
    const float shift = __fmul_rn((float)c, offv);

    // stage shifted boxes + areas with CONSTANT bound (no g_m dependency in prologue);
    // slots >= m hold stale-but-deterministic data and are never read.
    for (int t = tid; t < NBOX; t += 512) {
        float4 bx = g_sbox[c * NBOX + t];
        float4 sb = make_float4(__fadd_rn(bx.x, shift), __fadd_rn(bx.y, shift),
                                __fadd_rn(bx.z, shift), __fadd_rn(bx.w, shift));
        s_b[t] = sb;
        s_a[t] = __fmul_rn(__fsub_rn(sb.z, sb.x), __fsub_rn(sb.w, sb.y));
    }
    __syncthreads();

    // this block's 32-row mask tile (warps 0..12 carry words 0..12)
    // decision "iou > 0.5" division-free: uni>0 && inter > 0.5*uni
    {
        const int i = ty * 32 + lane;
        if (wd < NW && i < m) {
            unsigned int bits = 0;
            const int lo = wd * 32;
            const int hi = min(m, lo + 32);
            const int st = max(lo, i + 1);
            if (st < hi) {
                float4 bi = s_b[i];
                float  ai = s_a[i];
                #pragma unroll 4
                for (int jd = st; jd < hi; jd++) {
                    float4 bj = s_b[jd];
                    float iw = fmaxf(__fsub_rn(fminf(bi.z, bj.z), fmaxf(bi.x, bj.x)), 0.0f);
                    float ih = fmaxf(__fsub_rn(fminf(bi.w, bj.w), fmaxf(bi.y, bj.y)), 0.0f);
                    float inter = __fmul_rn(iw, ih);
                    float uni = __fsub_rn(__fadd_rn(ai, s_a[jd]), inter);
                    if (uni > 0.0f && inter > __fmul_rn(0.5f, uni)) bits |= 1u << (jd - lo);
                }
            }
            g_mask[(c * NW + wd) * NBOX + i] = bits;   // coalesced (lane = row)
        }
    }
    __threadfence();                               // release mask stores
    __syncthreads();
    if (tid == 0) {
        unsigned int r = atomicAdd(&g_tile[c], 1u);
        s_elect = (r == NTILE - 1) ? 1 : 0;        // last tile of this class proceeds
    }
    __syncthreads();
    if (!s_elect) return;

    // ================= elected block (one per class) =================
    __threadfence();                               // acquire peers' mask stores
    // reload transposed: read coalesced [w][i], write smem row-major (stride-13: conflict-free)
    for (int t = tid; t < NW * NBOX; t += 512) {
        int w = t / NBOX;
        int i = t - w * NBOX;
        if (i < m) s_mask[i * NW + w] = g_mask[(c * NW + w) * NBOX + i];
    }
    for (int t = tid; t < SORTN; t += 512)  s_skey[t] = g_skey[c * SORTN + t];
    __syncthreads();

    // greedy scan (warp 0): branchless data-flow chain, no predicated guards
    if (tid < 32) {
        const int rlane = (lane < NW) ? lane : (NW - 1);   // clamp: lanes >= 13 unused
        unsigned int mysup = 0;                    // lane w owns rows [32w, 32w+32)
        const int nb = (m + 31) >> 5;
        for (int b = 0; b < nb; b++) {
            unsigned int cur = __shfl_sync(FULLM, mysup, b);
            const int base = b << 5;
            const int rows = min(32, m - base);
            unsigned int wreg[32];
            #pragma unroll
            for (int q = 0; q < 32; q++)
                wreg[q] = (q < rows) ? s_mask[(base + q) * NW + b] : 0u;
            #pragma unroll
            for (int q = 0; q < 32; q++) {
                int rr = (q < rows) ? (base + q) : (m - 1);        // safe index
                unsigned int row = s_mask[rr * NW + rlane];        // off-chain LDS
                unsigned int gv  = (q < rows) ? 0u : FULLM;        // off-chain
                // take = all-ones iff row suppressed (bit q of cur) or q >= rows
                unsigned int take = (unsigned int)(((int)(cur << (31 - q))) >> 31) | gv;
                cur   |= wreg[q] & ~take;                          // chain: SHL,SHR,LOP3
                mysup |= row & ~take;                              // off-chain LOP3
            }
        }
        int cnt = 0;
        for (int bs = 0; bs < m; bs += 32) {
            int t = bs + lane;
            unsigned int supw = __shfl_sync(FULLM, mysup, t >> 5);
            bool kept = (t < m) && !((supw >> (t & 31)) & 1u);
            unsigned int bal = __ballot_sync(FULLM, kept);
            int pos = cnt + __popc(bal & ((1u << lane) - 1u));
            if (kept && pos < TOPK) g_selkey[c * TOPK + pos] = s_skey[t];
            cnt += __popc(bal);
        }
        cnt = min(cnt, TOPK);
        for (int p = cnt + lane; p < TOPK; p += 32) g_selkey[c * TOPK + p] = SENTK;
        __threadfence();                           // publish selkey stores
        __syncwarp();
        if (lane == 0) atomicAdd(&g_done, 1u);
    }
    __syncthreads();

    // rendezvous: all 20 classes' selkey visible (20 pollers only)
    if (tid == 0) {
        volatile unsigned int* vd = &g_done;
        while (*vd < (unsigned)NCLS) { }
        __threadfence();
    }
    __syncthreads();

    // load all 2000 candidates (512 threads -> 4 loads each, high MLP)
    for (int t = tid; t < NSEL; t += 512) s_sel[t] = g_selkey[t];
    __syncthreads();

    // merge-by-rank: rank own class's kept keys against the other 19 sorted lists
    if (tid < TOPK) {
        unsigned long long e = s_sel[c * TOPK + tid];
        if (e != SENTK) {
            int rank = tid;                        // position within own sorted list
            #pragma unroll
            for (int c2 = 0; c2 < NCLS; c2++) {
                if (c2 == c) continue;
                const unsigned long long* seg = s_sel + c2 * TOPK;
                int lo = 0;                        // lower_bound: #elements < e
                #pragma unroll
                for (int s = 64; s > 0; s >>= 1) {
                    int p = lo + s;
                    if (p <= TOPK && seg[p - 1] < e) lo = p;
                }
                rank += lo;
            }
            if (rank < TOPK) {
                unsigned int j = (unsigned int)e;
                int cc = (int)(j % NCLS);
                int b  = (int)(j / NCLS);
                int i  = cc * NBOX + b;
                float4 bx = reinterpret_cast<const float4*>(boxes)[i];
                out[rank * 4 + 0] = fminf(fmaxf(bx.x, 0.0f), IMGW);
                out[rank * 4 + 1] = fminf(fmaxf(bx.y, 0.0f), IMGH);
                out[rank * 4 + 2] = fminf(fmaxf(bx.z, 0.0f), IMGW);
                out[rank * 4 + 3] = fminf(fmaxf(bx.w, 0.0f), IMGH);
                out[4 * TOPK + rank] = inv_ord((unsigned int)(e >> 32));
                out[5 * TOPK + rank] = (float)pred_cls[i];
                out[6 * TOPK + rank] = 1.0f;
            }
        }
    }

    // last finisher resets globals for the next graph replay
    __syncthreads();
    if (tid == 0) {
        unsigned int r2 = atomicAdd(&g_done2, 1u);
        if (r2 == NCLS - 1) {
            g_maxBits = 0u;
            g_done    = 0u;
            g_done2   = 0u;
            #pragma unroll
            for (int c2 = 0; c2 < NCLS; c2++) g_tile[c2] = 0u;
            __threadfence();
        }
    }
}

// ---------------- launch ----------------
extern "C" void kernel_launch(void* const* d_in, const int* in_sizes, int n_in,
                              void* d_out, int out_size) {
    const int*   pred_cls = (const int*)d_in[0];
    const float* boxes    = (const float*)d_in[1];
    const float* scores   = (const float*)d_in[2];
    float* out = (float*)d_out;

    k1<<<NCLS, SORTN>>>(boxes, scores, out);
    kB<<<dim3(NTILE, NCLS), 512>>>(boxes, pred_cls, out);
}

// round 15
// speedup vs baseline: 2.1885x; 1.0501x over previous
#include <cuda_runtime.h>
#include <math_constants.h>

#define NCLS   20
#define NBOX   400
#define SORTN  512
#define IMGW   1333.0f
#define IMGH   800.0f
#define TOPK   100
#define NSEL   (NCLS * TOPK)     // 2000
#define NW     13                // 400 bits -> 13 u32 words
#define NTILE  13                // 13 x 32 rows = 416 >= 400
#define SENTK  0xFFFFFFFFFFFFFFFFull
#define FULLM  0xFFFFFFFFu

// ---------------- device scratch ----------------
__device__ unsigned long long g_skey[NCLS * SORTN];   // sorted keys per class
__device__ float4             g_sbox[NCLS * NBOX];    // clipped boxes in sorted order
__device__ int                g_m[NCLS];              // valid count per class
__device__ unsigned int       g_mask[NCLS * NW * NBOX]; // [class][word][row] -> coalesced
__device__ unsigned long long g_selkey[NSEL];         // per class: sorted kept top-100 (pad)
__device__ unsigned int       g_maxBits = 0u;
__device__ unsigned int       g_tile[NCLS];           // mask-tile completion counters
__device__ unsigned int       g_done    = 0u;
__device__ unsigned int       g_done2   = 0u;

// descending-sortable mapping (ascending u64 sort -> descending float score)
__device__ __forceinline__ unsigned int ord_desc(float f) {
    unsigned int u = __float_as_uint(f);
    unsigned int m = (u & 0x80000000u) ? ~u : (u | 0x80000000u);
    return ~m;
}
__device__ __forceinline__ float inv_ord(unsigned int o) {
    unsigned int m = ~o;
    unsigned int u = (m & 0x80000000u) ? (m & 0x7FFFFFFFu) : ~m;
    return __uint_as_float(u);
}
__device__ __forceinline__ unsigned long long shfl_xor_u64(unsigned long long v, int jj) {
    unsigned int lo = (unsigned int)v, hi = (unsigned int)(v >> 32);
    lo = __shfl_xor_sync(FULLM, lo, jj);
    hi = __shfl_xor_sync(FULLM, hi, jj);
    return ((unsigned long long)hi << 32) | lo;
}
__device__ __forceinline__ unsigned long long uminll(unsigned long long a, unsigned long long b) { return a < b ? a : b; }
__device__ __forceinline__ unsigned long long umaxll(unsigned long long a, unsigned long long b) { return a > b ? a : b; }
// sign-extend lowest bit to full mask: 0 -> 0x0, 1 -> 0xFFFFFFFF (single SGXT)
__device__ __forceinline__ unsigned int bit0_mask(unsigned int x) {
    unsigned int r;
    asm("szext.clamp.s32 %0, %1, 1;" : "=r"(r) : "r"(x));
    return r;
}

// ---------------- k1: per-class load/clip/key + hybrid bitonic sort (champion verbatim) --
__global__ void __launch_bounds__(SORTN) k1(const float* __restrict__ boxes,
                                            const float* __restrict__ scores,
                                            float* __restrict__ out) {
    __shared__ unsigned long long skey[SORTN];
    __shared__ float4       s_cbox[NBOX];
    __shared__ unsigned int s_wmax[16];

    const int cls = blockIdx.x, tid = threadIdx.x, lane = tid & 31;

    float lmax = 0.0f;
    bool  valid = false;
    unsigned long long v = SENTK;
    if (tid < NBOX) {
        float4 bx = reinterpret_cast<const float4*>(boxes)[cls * NBOX + tid];
        float2 sc = reinterpret_cast<const float2*>(scores)[cls * NBOX + tid];
        bool fin = isfinite(bx.x) && isfinite(bx.y) && isfinite(bx.z) && isfinite(bx.w)
                && isfinite(sc.x) && isfinite(sc.y);
        float x1 = fminf(fmaxf(bx.x, 0.0f), IMGW);
        float y1 = fminf(fmaxf(bx.y, 0.0f), IMGH);
        float x2 = fminf(fmaxf(bx.z, 0.0f), IMGW);
        float y2 = fminf(fmaxf(bx.w, 0.0f), IMGH);
        valid = fin && (sc.x > 0.05f);
        float masked = valid ? sc.x : -CUDART_INF_F;
        unsigned int j = (unsigned int)(tid * NCLS + cls);       // transposed index
        v = ((unsigned long long)ord_desc(masked) << 32) | j;
        s_cbox[tid] = make_float4(x1, y1, x2, y2);
        lmax = fmaxf(fmaxf(x1, x2), fmaxf(y1, y2));
    }
    unsigned int wb = __reduce_max_sync(FULLM, __float_as_uint(lmax));
    if (lane == 0) s_wmax[tid >> 5] = wb;
    const int m = __syncthreads_count(valid);
    if (tid == 0) {
        unsigned int mx = 0;
        #pragma unroll
        for (int w = 0; w < 16; w++) mx = max(mx, s_wmax[w]);
        atomicMax(&g_maxBits, mx);
    }

    // hybrid bitonic sort: smem stages jj>=32, shfl stages jj<=16
    for (int k = 2; k <= SORTN; k <<= 1) {
        for (int jj = k >> 1; jj >= 32; jj >>= 1) {
            skey[tid] = v;
            __syncthreads();
            unsigned long long p = skey[tid ^ jj];
            bool km = (((tid & k) == 0) == ((tid & jj) == 0));
            v = km ? uminll(v, p) : umaxll(v, p);
            __syncthreads();
        }
        int j0 = (k >> 1) < 16 ? (k >> 1) : 16;
        for (int jj = j0; jj >= 1; jj >>= 1) {
            unsigned long long p = shfl_xor_u64(v, jj);
            bool km = (((tid & k) == 0) == ((tid & jj) == 0));
            v = km ? uminll(v, p) : umaxll(v, p);
        }
    }

    g_skey[cls * SORTN + tid] = v;
    if (tid < m) {
        unsigned int j = (unsigned int)v;
        int b = (int)(j / NCLS);
        g_sbox[cls * NBOX + tid] = s_cbox[b];
    }
    if (tid == 0) g_m[cls] = m;

    // class-0 block pre-writes ALL default output rows; kB overwrites ranked rows
    if (cls == 0) {
        if (tid < 4 * TOPK) out[tid] = 0.0f;                  // boxes
        if (tid < TOPK) {
            out[4 * TOPK + tid] = 0.0f;                       // scores
            out[5 * TOPK + tid] = -1.0f;                      // cls
            out[6 * TOPK + tid] = 0.0f;                       // valid
        }
    }
}

// ---------------- kB: mask tile + last-tile election -> greedy + merge + output ----------
__global__ void __launch_bounds__(512) kB(const float* __restrict__ boxes,
                                          const int* __restrict__ pred_cls,
                                          float* __restrict__ out) {
    // buf1: s_b+s_a during mask phase; s_mask for elected block (disjoint in time)
    __shared__ __align__(16) unsigned char buf1[NBOX * NW * 4];     // 20.8 KB
    __shared__ __align__(16) unsigned long long s_sel[NSEL];        // 16 KB (elected only)
    __shared__ unsigned long long s_skey[SORTN];                    // 4 KB (elected only)
    __shared__ int s_elect;

    float4*       s_b    = reinterpret_cast<float4*>(buf1);                    // [NBOX]
    float*        s_a    = reinterpret_cast<float*>(buf1 + NBOX * 16);         // [NBOX]
    unsigned int* s_mask = reinterpret_cast<unsigned int*>(buf1);              // [NBOX*NW] row-major

    const int c   = blockIdx.y;                    // class
    const int ty  = blockIdx.x;                    // 32-row tile 0..12
    const int tid = threadIdx.x;
    const int wd  = tid >> 5, lane = tid & 31;
    const int m   = g_m[c];                        // overlaps with staging below

    const float offv  = __fadd_rn(__uint_as_float(g_maxBits), 1.0f);
    const float shift = __fmul_rn((float)c, offv);

    // triangular staging: this block only ever reads boxes t >= 32*ty (j > i >= 32ty)
    for (int t = 32 * ty + tid; t < NBOX; t += 512) {
        float4 bx = g_sbox[c * NBOX + t];
        float4 sb = make_float4(__fadd_rn(bx.x, shift), __fadd_rn(bx.y, shift),
                                __fadd_rn(bx.z, shift), __fadd_rn(bx.w, shift));
        s_b[t] = sb;
        s_a[t] = __fmul_rn(__fsub_rn(sb.z, sb.x), __fsub_rn(sb.w, sb.y));
    }
    __syncthreads();

    // this block's 32-row mask tile (warps 0..12 carry words 0..12)
    // "iou > 0.5" division-free: inter > 0.5*uni (uni >= 0 provable; uni=0 => inter=0)
    {
        const int i = ty * 32 + lane;
        if (wd < NW && i < m) {
            unsigned int bits = 0;
            const int lo = wd * 32;
            const int hi = min(m, lo + 32);
            const int st = max(lo, i + 1);
            if (st < hi) {
                float4 bi = s_b[i];
                float  ai = s_a[i];
                #pragma unroll 4
                for (int jd = st; jd < hi; jd++) {
                    float4 bj = s_b[jd];
                    float iw = fmaxf(__fsub_rn(fminf(bi.z, bj.z), fmaxf(bi.x, bj.x)), 0.0f);
                    float ih = fmaxf(__fsub_rn(fminf(bi.w, bj.w), fmaxf(bi.y, bj.y)), 0.0f);
                    float inter = __fmul_rn(iw, ih);
                    float uni = __fsub_rn(__fadd_rn(ai, s_a[jd]), inter);
                    if (inter > __fmul_rn(0.5f, uni)) bits |= 1u << (jd - lo);
                }
            }
            g_mask[(c * NW + wd) * NBOX + i] = bits;   // coalesced (lane = row)
        }
    }
    __threadfence();                               // release mask stores
    __syncthreads();
    if (tid == 0) {
        unsigned int r = atomicAdd(&g_tile[c], 1u);
        s_elect = (r == NTILE - 1) ? 1 : 0;        // last tile of this class proceeds
    }
    __syncthreads();
    if (!s_elect) return;

    // ================= elected block (one per class) =================
    __threadfence();                               // acquire peers' mask stores
    // reload transposed: read coalesced [w][i], write smem row-major (stride-13: conflict-free)
    for (int t = tid; t < NW * NBOX; t += 512) {
        int w = t / NBOX;
        int i = t - w * NBOX;
        if (i < m) s_mask[i * NW + w] = g_mask[(c * NW + w) * NBOX + i];
    }
    for (int t = tid; t < SORTN; t += 512)  s_skey[t] = g_skey[c * SORTN + t];
    __syncthreads();

    // greedy scan (warp 0): shifted-state chain, 2 dependent ops per row
    // curs = cur >> q; take = sign-ext of bit0(curs); curs' = (curs>>1) | (W'q & ~take)
    if (tid < 32) {
        const int rlane = (lane < NW) ? lane : (NW - 1);   // clamp: lanes >= 13 unused
        unsigned int mysup = 0;                    // lane w owns rows [32w, 32w+32)
        const int nb = (m + 31) >> 5;
        for (int b = 0; b < nb; b++) {
            const int base = b << 5;
            const int rows = min(32, m - base);
            unsigned int pad = (rows < 32) ? (FULLM << rows) : 0u;  // rows>=m => suppressed
            unsigned int curs = __shfl_sync(FULLM, mysup, b) | pad;
            unsigned int wreg[32];
            #pragma unroll
            for (int q = 0; q < 32; q++)
                wreg[q] = (q < rows) ? s_mask[(base + q) * NW + b] : 0u;
            #pragma unroll
            for (int q = 0; q < 32; q++) {
                int rr = min(base + q, NBOX - 1);                  // safe smem index
                unsigned int row = s_mask[rr * NW + rlane];        // off-chain LDS
                unsigned int Wq  = (q < 31) ? (wreg[q] >> (q + 1)) : 0u;  // off-chain
                unsigned int take = bit0_mask(curs);               // chain lvl 1 (SGXT)
                curs = (curs >> 1) | (Wq & ~take);                 // chain lvl 2 (SHF||,LOP3)
                mysup |= row & ~take;                              // off-chain LOP3
            }
        }
        int cnt = 0;
        for (int bs = 0; bs < m; bs += 32) {
            int t = bs + lane;
            unsigned int supw = __shfl_sync(FULLM, mysup, t >> 5);
            bool kept = (t < m) && !((supw >> (t & 31)) & 1u);
            unsigned int bal = __ballot_sync(FULLM, kept);
            int pos = cnt + __popc(bal & ((1u << lane) - 1u));
            if (kept && pos < TOPK) g_selkey[c * TOPK + pos] = s_skey[t];
            cnt += __popc(bal);
        }
        cnt = min(cnt, TOPK);
        for (int p = cnt + lane; p < TOPK; p += 32) g_selkey[c * TOPK + p] = SENTK;
        __threadfence();                           // publish selkey stores
        __syncwarp();
        if (lane == 0) atomicAdd(&g_done, 1u);
    }
    __syncthreads();

    // rendezvous: all 20 classes' selkey visible (20 pollers only)
    if (tid == 0) {
        volatile unsigned int* vd = &g_done;
        while (*vd < (unsigned)NCLS) { }
        __threadfence();
    }
    __syncthreads();

    // load all 2000 candidates (512 threads -> 4 loads each, high MLP)
    for (int t = tid; t < NSEL; t += 512) s_sel[t] = g_selkey[t];
    __syncthreads();

    // merge-by-rank: rank own class's kept keys against the other 19 sorted lists
    if (tid < TOPK) {
        unsigned long long e = s_sel[c * TOPK + tid];
        if (e != SENTK) {
            int rank = tid;                        // position within own sorted list
            #pragma unroll
            for (int c2 = 0; c2 < NCLS; c2++) {
                if (c2 == c) continue;
                const unsigned long long* seg = s_sel + c2 * TOPK;
                int lo = 0;                        // lower_bound: #elements < e
                #pragma unroll
                for (int s = 64; s > 0; s >>= 1) {
                    int p = lo + s;
                    if (p <= TOPK && seg[p - 1] < e) lo = p;
                }
                rank += lo;
            }
            if (rank < TOPK) {
                unsigned int j = (unsigned int)e;
                int cc = (int)(j % NCLS);
                int b  = (int)(j / NCLS);
                int i  = cc * NBOX + b;
                float4 bx = reinterpret_cast<const float4*>(boxes)[i];
                out[rank * 4 + 0] = fminf(fmaxf(bx.x, 0.0f), IMGW);
                out[rank * 4 + 1] = fminf(fmaxf(bx.y, 0.0f), IMGH);
                out[rank * 4 + 2] = fminf(fmaxf(bx.z, 0.0f), IMGW);
                out[rank * 4 + 3] = fminf(fmaxf(bx.w, 0.0f), IMGH);
                out[4 * TOPK + rank] = inv_ord((unsigned int)(e >> 32));
                out[5 * TOPK + rank] = (float)pred_cls[i];
                out[6 * TOPK + rank] = 1.0f;
            }
        }
    }

    // last finisher resets globals for the next graph replay
    __syncthreads();
    if (tid == 0) {
        unsigned int r2 = atomicAdd(&g_done2, 1u);
        if (r2 == NCLS - 1) {
            g_maxBits = 0u;
            g_done    = 0u;
            g_done2   = 0u;
            #pragma unroll
            for (int c2 = 0; c2 < NCLS; c2++) g_tile[c2] = 0u;
            __threadfence();
        }
    }
}

// ---------------- launch ----------------
extern "C" void kernel_launch(void* const* d_in, const int* in_sizes, int n_in,
                              void* d_out, int out_size) {
    const int*   pred_cls = (const int*)d_in[0];
    const float* boxes    = (const float*)d_in[1];
    const float* scores   = (const float*)d_in[2];
    float* out = (float*)d_out;

    k1<<<NCLS, SORTN>>>(boxes, scores, out);
    kB<<<dim3(NTILE, NCLS), 512>>>(boxes, pred_cls, out);
}